// round 17
// baseline (speedup 1.0000x reference)
#include <cuda_runtime.h>
#include <cuda_fp16.h>
#include <math.h>
#include <stdint.h>

#define Bn   512
#define Nn   199
#define Hn   4
#define Fn   64
#define Un   64
#define OUTC 455           // H*U + N
#define MT   13            // m16 tiles covering 200 rows (208)
#define JT8  25            // j-tiles of 8 (dense output)
#define NT16 13            // node k16-tiles (208)
#define FKT  4             // f k16-tiles (64)
#define FT   8             // f/u 8-tiles
#define THREADS 512
#define XSTh 208           // XsT half-stride (416B == 32 mod 128: conflict-free)
#define EBWh (16 * 208)    // e-buffer halves per warp

// Preprocessed fp16 operand banks (global, L2-resident)
__device__ __align__(16) uint32_t g_GaH[Hn * MT * NT16 * 128];  // feat A-frags (k16)
__device__ __align__(16) uint32_t g_KbH[Hn * JT8 * FKT * 64];   // dense B-frags, kt-pair packed
__device__ __align__(16) uint32_t g_FbH[Hn * FT * FKT * 64];    // fc B-frags, kt-pair packed
__device__ __align__(16) float    g_Ac [MT * JT8 * 128];        // adjacency C-frag fp32

#define GA16_N (Hn * MT * NT16 * 128)
#define KB16_N (Hn * JT8 * FKT * 64)
#define FB16_N (Hn * FT * FKT * 64)
#define AC_N   (MT * JT8 * 128)

__device__ __forceinline__ void mma_f16(float c[4],
    uint32_t a0, uint32_t a1, uint32_t a2, uint32_t a3,
    uint32_t b0, uint32_t b1) {
    asm volatile(
        "mma.sync.aligned.m16n8k16.row.col.f32.f16.f16.f32 "
        "{%0,%1,%2,%3}, {%4,%5,%6,%7}, {%8,%9}, {%0,%1,%2,%3};"
        : "+f"(c[0]), "+f"(c[1]), "+f"(c[2]), "+f"(c[3])
        : "r"(a0), "r"(a1), "r"(a2), "r"(a3), "r"(b0), "r"(b1));
}
__device__ __forceinline__ uint32_t pkh2(float lo, float hi) {
    __half2 h = __floats2half2_rn(lo, hi);       // .x = lo (low 16 bits)
    return *reinterpret_cast<uint32_t*>(&h);
}
__device__ __forceinline__ uint32_t hmul2u(uint32_t a, __half2 s) {
    __half2 av = *reinterpret_cast<__half2*>(&a);
    __half2 r = __hmul2(av, s);
    return *reinterpret_cast<uint32_t*>(&r);
}
// node column w (0..15) -> permuted slot: pairs (2c,2c+1,2c+8,2c+9) adjacent
__device__ __forceinline__ int nslot(int w) {
    return 4 * ((w & 7) >> 1) + (w & 1) + 2 * (w >> 3);
}

// ---------------- fused operand prep (single launch) ----------------
// g_KbH / g_FbH layout: [h][tile][kp(2)][lane(32)][c(4)] where the 4 u32s are
// (kt=2kp r0, kt=2kp r1, kt=2kp+1 r0, kt=2kp+1 r1) -> one uint4 per (tile,kp,lane).
__global__ void prep_all(const float* __restrict__ A, const float* __restrict__ P,
                         const float* __restrict__ KER, const float* __restrict__ FC) {
    int t = blockIdx.x * blockDim.x + threadIdx.x;
    if (t < GA16_N) {
        int r = t & 3, lane = (t >> 2) & 31, rest = t >> 7;
        int kt = rest % NT16; rest /= NT16;
        int mt = rest % MT;  int h = rest / MT;
        int m  = 16 * mt + (lane >> 2) + (r & 1) * 8;
        int n0 = 16 * kt + 2 * (lane & 3) + (r >> 1) * 8;
        float v0 = (m < Nn && n0     < Nn) ? A[n0 * Nn + m] * P[(h * Nn + n0) * Nn + m] : 0.f;
        float v1 = (m < Nn && n0 + 1 < Nn) ? A[(n0 + 1) * Nn + m] * P[(h * Nn + n0 + 1) * Nn + m] : 0.f;
        g_GaH[t] = pkh2(v0, v1);
        return;
    }
    t -= GA16_N;
    if (t < KB16_N) {
        int c = t & 3, lane = (t >> 2) & 31, rest = t >> 7;
        int kp = rest & 1; rest >>= 1;
        int jt = rest % JT8; int h = rest / JT8;
        int kt = 2 * kp + (c >> 1), r = c & 1;
        int f0 = 16 * kt + 2 * (lane & 3) + r * 8;
        int j  = 8 * jt + (lane >> 2);
        float v0 = (j < Nn) ? KER[(h * Fn + f0) * Nn + j] : 0.f;
        float v1 = (j < Nn) ? KER[(h * Fn + f0 + 1) * Nn + j] : 0.f;
        g_KbH[t] = pkh2(v0, v1);
        return;
    }
    t -= KB16_N;
    if (t < FB16_N) {
        int c = t & 3, lane = (t >> 2) & 31, rest = t >> 7;
        int kp = rest & 1; rest >>= 1;
        int ut = rest & 7; int h = rest >> 3;
        int kt = 2 * kp + (c >> 1), r = c & 1;
        int f0 = 16 * kt + 2 * (lane & 3) + r * 8;
        int u  = 8 * ut + (lane >> 2);
        g_FbH[t] = pkh2(FC[(h * Fn + f0) * Un + u], FC[(h * Fn + f0 + 1) * Un + u]);
        return;
    }
    t -= FB16_N;
    if (t < AC_N) {
        int i = t & 3, lane = (t >> 2) & 31, rest = t >> 7;
        int jt = rest % JT8; int mt = rest / JT8;
        int r = (lane >> 2) + (i >> 1) * 8;
        int j = 8 * jt + 2 * (lane & 3) + (i & 1);
        int m = 16 * mt + r;
        g_Ac[t] = (m < Nn && j < Nn) ? A[m * Nn + j] : 0.f;
    }
}

// ---------------- main fused kernel ----------------
__global__ __launch_bounds__(THREADS, 2)
void gc_kernel(const float* __restrict__ X, const float* __restrict__ B1,
               const float* __restrict__ B2, float* __restrict__ out)
{
    extern __shared__ __align__(16) char smraw[];
    __half* XsT  = (__half*)smraw;             // [64][XSTh] fp16 X^T, pair-permuted
    __half* ebuf = XsT + Fn * XSTh;            // [MT][16][XSTh] fp16 e staging
    float*  b1s  = (float*)(ebuf + MT * EBWh); // [200] fp32

    const int b = blockIdx.x / Hn;
    const int h = blockIdx.x - b * Hn;
    const int tid = threadIdx.x;
    const int w = tid >> 5;
    const int lane = tid & 31;
    const bool last_h = (h == Hn - 1);

    for (int i = tid; i < 208 * Fn; i += THREADS) {
        int n = i >> 6, f = i & 63;
        float v = (n < Nn) ? X[((size_t)b * Nn + n) * Fn + f] : 0.f;
        int col = (n & ~15) + nslot(n & 15);
        XsT[f * XSTh + col] = __float2half_rn(v);
    }
    // zero the pad region of every warp's e-buffer (node cols 192..207)
    for (int i = tid; i < MT * 16 * 8; i += THREADS) {
        int wb = i >> 7, row = (i >> 3) & 15, cc = i & 7;
        *(uint32_t*)&ebuf[wb * EBWh + row * XSTh + 192 + 2 * cc] = 0u;
    }
    for (int i = tid; i < 200; i += THREADS) b1s[i] = (i < Nn) ? B1[h * Nn + i] : 0.f;
    __syncthreads();

    if (w >= MT) return;
    const int m0 = 16 * w;
    const int g = lane >> 2;                 // row group within tile
    const int q = lane & 3;
    const int mA = m0 + g;                   // rows for c0/c1
    const int mB = mA + 8;                   // rows for c2/c3
    const int pairOff = 2 * q;
    __half* eb = ebuf + w * EBWh;            // [16][XSTh]

    // ======== FEAT: fC[ft] = G(m-tile) @ X  (13 k16-tiles, ping-pong) ========
    float fC[FT][4];
    #pragma unroll
    for (int t = 0; t < FT; t++) { fC[t][0]=fC[t][1]=fC[t][2]=fC[t][3]=0.f; }
    {
        const uint4* gaP = ((const uint4*)g_GaH) + ((size_t)(h * MT + w) * NT16) * 32 + lane;
        uint4 gaA = __ldg(gaP), gaB;
        #pragma unroll 1
        for (int k2 = 0; k2 < 7; k2++) {
            const int ktA = 2 * k2, ktB = ktA + 1;
            const bool hasB = (ktB < NT16);
            if (hasB) gaB = __ldg(gaP + ktB * 32);
            #pragma unroll
            for (int ft = 0; ft < FT; ft++) {
                uint2 xv = *(const uint2*)&XsT[(8 * ft + g) * XSTh + 16 * ktA + 4 * q];
                mma_f16(fC[ft], gaA.x, gaA.y, gaA.z, gaA.w, xv.x, xv.y);
            }
            if (ktA + 2 < NT16) gaA = __ldg(gaP + (ktA + 2) * 32);
            if (hasB) {
                #pragma unroll
                for (int ft = 0; ft < FT; ft++) {
                    uint2 xv = *(const uint2*)&XsT[(8 * ft + g) * XSTh + 16 * ktB + 4 * q];
                    mma_f16(fC[ft], gaB.x, gaB.y, gaB.z, gaB.w, xv.x, xv.y);
                }
            }
        }
    }
    // pack feat C -> k16 A-frags in-lane (adjacent C cols = fp16x2 pair; NO shuffles)
    uint32_t fA[FKT][4];
    #pragma unroll
    for (int kt = 0; kt < FKT; kt++) {
        fA[kt][0] = pkh2(fC[2*kt][0],   fC[2*kt][1]);
        fA[kt][1] = pkh2(fC[2*kt][2],   fC[2*kt][3]);
        fA[kt][2] = pkh2(fC[2*kt+1][0], fC[2*kt+1][1]);
        fA[kt][3] = pkh2(fC[2*kt+1][2], fC[2*kt+1][3]);
    }

    // ======== PASS A: DENSE + masked exp -> fp16 e-buffer (ping-pong) ========
    float s0 = 0.f, s1 = 0.f;
    {
        const uint4*  kbP = ((const uint4*)g_KbH) + (size_t)h * (JT8 * 2 * 32) + lane;
        const float4* acP = ((const float4*)g_Ac) + (size_t)w * (JT8 * 32) + lane;

        uint4 kA0 = __ldg(kbP), kA1 = __ldg(kbP + 32);
        float4 acA = __ldg(acP);
        uint4 kB0, kB1; float4 acB;

        #pragma unroll 1
        for (int it = 0; it < 13; it++) {
            const int jtA = 2 * it, jtB = jtA + 1;
            const bool hasB = (jtB < JT8);

            if (hasB) {
                kB0 = __ldg(kbP + (jtB * 2) * 32);
                kB1 = __ldg(kbP + (jtB * 2 + 1) * 32);
                acB = __ldg(acP + jtB * 32);
            }
            // ---- tile A
            {
                float d0[4] = {0.f,0.f,0.f,0.f};
                float d1[4] = {0.f,0.f,0.f,0.f};
                mma_f16(d0, fA[0][0],fA[0][1],fA[0][2],fA[0][3], kA0.x, kA0.y);
                mma_f16(d1, fA[1][0],fA[1][1],fA[1][2],fA[1][3], kA0.z, kA0.w);
                mma_f16(d0, fA[2][0],fA[2][1],fA[2][2],fA[2][3], kA1.x, kA1.y);
                mma_f16(d1, fA[3][0],fA[3][1],fA[3][2],fA[3][3], kA1.z, kA1.w);

                int j = 8 * jtA + pairOff;
                float2 b1v = *(const float2*)&b1s[j];
                float e0 = acA.x * __expf(d0[0] + d1[0] + b1v.x);
                float e1 = acA.y * __expf(d0[1] + d1[1] + b1v.y);
                float e2 = acA.z * __expf(d0[2] + d1[2] + b1v.x);
                float e3 = acA.w * __expf(d0[3] + d1[3] + b1v.y);
                s0 += e0 + e1; s1 += e2 + e3;

                int ecol = 16 * it + 4 * q;              // jtA even: slot pair +0
                *(uint32_t*)&eb[g * XSTh + ecol]       = pkh2(e0, e1);
                *(uint32_t*)&eb[(g + 8) * XSTh + ecol] = pkh2(e2, e3);

                if (last_h) {
                    if (mA < Nn) {
                        float* o = out + ((size_t)b * Nn + mA) * OUTC + Hn * Un + j;
                        o[0] = e0; if (j < 198) o[1] = e1;
                    }
                    if (mB < Nn) {
                        float* o = out + ((size_t)b * Nn + mB) * OUTC + Hn * Un + j;
                        o[0] = e2; if (j < 198) o[1] = e3;
                    }
                }
            }
            if (jtA + 2 < JT8) {    // prefetch next tile A while B computes
                kA0 = __ldg(kbP + ((jtA + 2) * 2) * 32);
                kA1 = __ldg(kbP + ((jtA + 2) * 2 + 1) * 32);
                acA = __ldg(acP + (jtA + 2) * 32);
            }
            // ---- tile B
            if (hasB) {
                float d0[4] = {0.f,0.f,0.f,0.f};
                float d1[4] = {0.f,0.f,0.f,0.f};
                mma_f16(d0, fA[0][0],fA[0][1],fA[0][2],fA[0][3], kB0.x, kB0.y);
                mma_f16(d1, fA[1][0],fA[1][1],fA[1][2],fA[1][3], kB0.z, kB0.w);
                mma_f16(d0, fA[2][0],fA[2][1],fA[2][2],fA[2][3], kB1.x, kB1.y);
                mma_f16(d1, fA[3][0],fA[3][1],fA[3][2],fA[3][3], kB1.z, kB1.w);

                int j = 8 * jtB + pairOff;
                float2 b1v = *(const float2*)&b1s[j];
                float e0 = acB.x * __expf(d0[0] + d1[0] + b1v.x);
                float e1 = acB.y * __expf(d0[1] + d1[1] + b1v.y);
                float e2 = acB.z * __expf(d0[2] + d1[2] + b1v.x);
                float e3 = acB.w * __expf(d0[3] + d1[3] + b1v.y);
                s0 += e0 + e1; s1 += e2 + e3;

                int ecol = 16 * it + 4 * q + 2;          // jtB odd: slot pair +2
                *(uint32_t*)&eb[g * XSTh + ecol]       = pkh2(e0, e1);
                *(uint32_t*)&eb[(g + 8) * XSTh + ecol] = pkh2(e2, e3);

                if (last_h) {
                    if (mA < Nn) {
                        float* o = out + ((size_t)b * Nn + mA) * OUTC + Hn * Un + j;
                        o[0] = e0; if (j < 198) o[1] = e1;
                    }
                    if (mB < Nn) {
                        float* o = out + ((size_t)b * Nn + mB) * OUTC + Hn * Un + j;
                        o[0] = e2; if (j < 198) o[1] = e3;
                    }
                }
            }
        }
    }
    s0 += __shfl_xor_sync(~0u, s0, 1); s0 += __shfl_xor_sync(~0u, s0, 2);
    s1 += __shfl_xor_sync(~0u, s1, 1); s1 += __shfl_xor_sync(~0u, s1, 2);
    const float inv0 = (s0 > 0.f) ? 1.f / s0 : 0.f;
    const float inv1 = (s1 > 0.f) ? 1.f / s1 : 0.f;
    __syncwarp();     // cross-lane visibility of eb before pass B

    if (last_h) {     // rescale raw mask in-place (same thread wrote it)
        #pragma unroll 1
        for (int jt = 0; jt < JT8; jt++) {
            int j = 8 * jt + pairOff;
            if (mA < Nn) {
                float* o = out + ((size_t)b * Nn + mA) * OUTC + Hn * Un + j;
                o[0] *= inv0; if (j < 198) o[1] *= inv0;
            }
            if (mB < Nn) {
                float* o = out + ((size_t)b * Nn + mB) * OUTC + Hn * Un + j;
                o[0] *= inv1; if (j < 198) o[1] *= inv1;
            }
        }
    }

    // ======== PASS B: NODE = (e*inv) @ X over 13 j k16-tiles, shuffle-free ====
    const __half2 hi0 = __float2half2_rn(inv0);
    const __half2 hi1 = __float2half2_rn(inv1);
    float nC[FT][4];
    #pragma unroll
    for (int t = 0; t < FT; t++) { nC[t][0]=nC[t][1]=nC[t][2]=nC[t][3]=0.f; }

    #pragma unroll 1
    for (int jt = 0; jt < NT16; jt++) {
        uint2 aLo = *(const uint2*)&eb[g * XSTh + 16 * jt + 4 * q];       // (g, k), (g, k+8)
        uint2 aHi = *(const uint2*)&eb[(g + 8) * XSTh + 16 * jt + 4 * q]; // (g+8, ...)
        uint32_t a0 = hmul2u(aLo.x, hi0), a2 = hmul2u(aLo.y, hi0);
        uint32_t a1 = hmul2u(aHi.x, hi1), a3 = hmul2u(aHi.y, hi1);
        #pragma unroll
        for (int ft = 0; ft < FT; ft++) {
            uint2 xv = *(const uint2*)&XsT[(8 * ft + g) * XSTh + 16 * jt + 4 * q];
            mma_f16(nC[ft], a0, a1, a2, a3, xv.x, xv.y);
        }
    }

    // pack node C -> k16 A-frags in-lane (normalized already; NO shuffles)
    uint32_t nA[FKT][4];
    #pragma unroll
    for (int kt = 0; kt < FKT; kt++) {
        nA[kt][0] = pkh2(nC[2*kt][0],   nC[2*kt][1]);
        nA[kt][1] = pkh2(nC[2*kt][2],   nC[2*kt][3]);
        nA[kt][2] = pkh2(nC[2*kt+1][0], nC[2*kt+1][1]);
        nA[kt][3] = pkh2(nC[2*kt+1][2], nC[2*kt+1][3]);
    }

    // ======== FC: out = node @ fc + b2 ========
    const uint4* fbP = ((const uint4*)g_FbH) + (size_t)h * (FT * 2 * 32) + lane;
    #pragma unroll 1
    for (int ut = 0; ut < FT; ut++) {
        float o0[4] = {0.f,0.f,0.f,0.f};
        float o1[4] = {0.f,0.f,0.f,0.f};
        uint4 f0 = __ldg(fbP + (ut * 2) * 32);
        uint4 f1 = __ldg(fbP + (ut * 2 + 1) * 32);
        mma_f16(o0, nA[0][0],nA[0][1],nA[0][2],nA[0][3], f0.x, f0.y);
        mma_f16(o1, nA[1][0],nA[1][1],nA[1][2],nA[1][3], f0.z, f0.w);
        mma_f16(o0, nA[2][0],nA[2][1],nA[2][2],nA[2][3], f1.x, f1.y);
        mma_f16(o1, nA[3][0],nA[3][1],nA[3][2],nA[3][3], f1.z, f1.w);

        int u = 8 * ut + pairOff;
        float b2x = __ldg(&B2[h * Un + u]);
        float b2y = __ldg(&B2[h * Un + u + 1]);
        if (mA < Nn) {
            float* o = out + ((size_t)b * Nn + mA) * OUTC + h * Un + u;
            o[0] = o0[0] + o1[0] + b2x; o[1] = o0[1] + o1[1] + b2y;
        }
        if (mB < Nn) {
            float* o = out + ((size_t)b * Nn + mB) * OUTC + h * Un + u;
            o[0] = o0[2] + o1[2] + b2x; o[1] = o0[3] + o1[3] + b2y;
        }
    }
}

static const size_t SMEM_BYTES =
    (size_t)(Fn * XSTh + MT * EBWh) * 2 + 200 * 4;   // 113,952 B (2 blocks/SM)

extern "C" void kernel_launch(void* const* d_in, const int* in_sizes, int n_in,
                              void* d_out, int out_size) {
    const float* X   = (const float*)d_in[0];
    const float* A   = (const float*)d_in[1];
    const float* KER = (const float*)d_in[2];
    const float* P   = (const float*)d_in[3];
    const float* FC  = (const float*)d_in[4];
    const float* B1  = (const float*)d_in[5];
    const float* B2  = (const float*)d_in[6];
    float* out = (float*)d_out;

    const int PREP_TOTAL = GA16_N + KB16_N + FB16_N + AC_N;
    prep_all<<<(PREP_TOTAL + 255) / 256, 256>>>(A, P, KER, FC);

    cudaFuncSetAttribute(gc_kernel, cudaFuncAttributeMaxDynamicSharedMemorySize,
                         (int)SMEM_BYTES);
    gc_kernel<<<Bn * Hn, THREADS, SMEM_BYTES>>>(X, B1, B2, out);
}